// round 1
// baseline (speedup 1.0000x reference)
#include <cuda_runtime.h>

// Density_Block: out[i] = lerp of softmax(x[i,:] @ W + b) at grid cols L/U derived from t[i].
// N = 524288, IND = 128, OUTD = 256 (NUM_GRID = 255).
//
// Fused GEMM + softmax-statistics + gather. Never materializes softmax:
// each row needs only rowmax, sum(exp), exp(logit[Li]), exp(logit[Ui]).

#define NGRID 255
#define OUTD  256
#define IND   128
#define RPB   64     // rows per block
#define BK    16     // k-chunk staged in smem

__global__ void __launch_bounds__(256)
density_kernel(const float* __restrict__ t,
               const float* __restrict__ x,
               const float* __restrict__ w,
               const float* __restrict__ bias,
               float* __restrict__ out)
{
    __shared__ float xs[BK][RPB];    // transposed x tile: xs[kk][row]
    __shared__ float ws[BK][OUTD];   // w tile: ws[kk][col]

    const int tid   = threadIdx.x;
    const int warp  = tid >> 5;          // 8 warps; warp owns 8 full rows
    const int lane  = tid & 31;
    const int row0  = blockIdx.x * RPB;
    const int rbase = warp * 8;          // block-local first row of this warp
    const int cbase = lane * 4;          // lane owns cols [cbase,cbase+4) and [128+cbase,128+cbase+4)

    float acc[8][8];
    #pragma unroll
    for (int i = 0; i < 8; i++)
        #pragma unroll
        for (int j = 0; j < 8; j++) acc[i][j] = 0.f;

    for (int k0 = 0; k0 < IND; k0 += BK) {
        // ---- stage x tile (64 rows x 16 k), transposed into smem ----
        {
            int r  = tid >> 2;            // 0..63
            int kk = (tid & 3) << 2;      // 0,4,8,12
            float4 v = *reinterpret_cast<const float4*>(
                &x[(size_t)(row0 + r) * IND + k0 + kk]);
            xs[kk + 0][r] = v.x;
            xs[kk + 1][r] = v.y;
            xs[kk + 2][r] = v.z;
            xs[kk + 3][r] = v.w;
        }
        // ---- stage w tile (16 k x 256 cols) ----
        {
            int kk = tid >> 4;            // 0..15
            int cc = (tid & 15) << 4;     // 0..240 step 16
            const float4* src = reinterpret_cast<const float4*>(
                &w[(size_t)(k0 + kk) * OUTD + cc]);
            float4* dst = reinterpret_cast<float4*>(&ws[kk][cc]);
            dst[0] = src[0]; dst[1] = src[1]; dst[2] = src[2]; dst[3] = src[3];
        }
        __syncthreads();

        #pragma unroll
        for (int kk = 0; kk < BK; kk++) {
            float xf[8], wf[8];
            #pragma unroll
            for (int i = 0; i < 8; i++) xf[i] = xs[kk][rbase + i];  // warp-uniform broadcast
            float4 w0 = *reinterpret_cast<const float4*>(&ws[kk][cbase]);         // conflict-free LDS.128
            float4 w1 = *reinterpret_cast<const float4*>(&ws[kk][128 + cbase]);
            wf[0] = w0.x; wf[1] = w0.y; wf[2] = w0.z; wf[3] = w0.w;
            wf[4] = w1.x; wf[5] = w1.y; wf[6] = w1.z; wf[7] = w1.w;
            #pragma unroll
            for (int i = 0; i < 8; i++)
                #pragma unroll
                for (int j = 0; j < 8; j++)
                    acc[i][j] = fmaf(xf[i], wf[j], acc[i][j]);
        }
        __syncthreads();
    }

    // ---- add bias ----
    float bf[8];
    #pragma unroll
    for (int j = 0; j < 4; j++) {
        bf[j]     = bias[cbase + j];
        bf[4 + j] = bias[128 + cbase + j];
    }
    #pragma unroll
    for (int i = 0; i < 8; i++)
        #pragma unroll
        for (int j = 0; j < 8; j++)
            acc[i][j] += bf[j];

    // ---- per-row softmax stats + data-dependent 2-point gather ----
    #pragma unroll
    for (int i = 0; i < 8; i++) {
        const int row = row0 + rbase + i;

        float m = acc[i][0];
        #pragma unroll
        for (int j = 1; j < 8; j++) m = fmaxf(m, acc[i][j]);
        #pragma unroll
        for (int off = 16; off > 0; off >>= 1)
            m = fmaxf(m, __shfl_xor_sync(0xffffffffu, m, off));

        float e[8], s = 0.f;
        #pragma unroll
        for (int j = 0; j < 8; j++) { e[j] = __expf(acc[i][j] - m); s += e[j]; }

        // grid indices (all lanes compute identically; t[row] is a broadcast load)
        const float tv    = t[row];
        const float tg    = tv * (float)NGRID;
        const float U     = ceilf(tg);
        const float inter = 1.0f - (U - tg);
        float Lf = U - 1.0f;
        if (Lf < 0.f) Lf = 0.f;   // t == 0 case
        const int Li = (int)Lf;
        const int Ui = (int)U;

        // one-hot gather: exactly one lane holds each column
        float gl = 0.f, gu = 0.f;
        int d;
        d = Li - cbase;         if (d >= 0 && d < 4) gl = e[d];
        d = Li - 128 - cbase;   if (d >= 0 && d < 4) gl = e[4 + d];
        d = Ui - cbase;         if (d >= 0 && d < 4) gu = e[d];
        d = Ui - 128 - cbase;   if (d >= 0 && d < 4) gu = e[4 + d];

        #pragma unroll
        for (int off = 16; off > 0; off >>= 1) {
            s  += __shfl_xor_sync(0xffffffffu, s,  off);
            gl += __shfl_xor_sync(0xffffffffu, gl, off);
            gu += __shfl_xor_sync(0xffffffffu, gu, off);
        }

        if (lane == 0) {
            const float pl = gl / s;
            const float pu = gu / s;
            out[row] = pl + (pu - pl) * inter;
        }
    }
}

extern "C" void kernel_launch(void* const* d_in, const int* in_sizes, int n_in,
                              void* d_out, int out_size)
{
    const float* t    = (const float*)d_in[0];
    const float* x    = (const float*)d_in[1];
    const float* w    = (const float*)d_in[2];
    const float* bias = (const float*)d_in[3];
    float* out        = (float*)d_out;

    const int n      = in_sizes[0];     // 524288
    const int blocks = n / RPB;         // divisible: 8192 blocks
    density_kernel<<<blocks, 256>>>(t, x, w, bias, out);
}

// round 3
// speedup vs baseline: 3.4039x; 3.4039x over previous
#include <cuda_runtime.h>
#include <cuda_bf16.h>
#include <cstdint>

// ============================================================================
// Density_Block via register-level bf16 tensor-core MMA (mma.sync m16n8k16).
// out[i] = lerp of softmax(x[i,:] @ W + b) at data-dependent cols L/U.
// N=524288, IND=128, OUTD=256. Split-precision bf16 (3 products, fp32 acc).
// Persistent kernel: W staged in smem once; warps stream 16-row stripes.
// ============================================================================

#define IND    128
#define OUTD   256
#define WPITCH 264      // padded bf16 pitch: 528B row stride -> conflict-free ldmatrix

#define SM_WHI  0
#define SM_WLO  (IND * WPITCH * 2)          // 67584
#define SM_BIAS (2 * IND * WPITCH * 2)      // 135168
#define SM_TOTAL (SM_BIAS + OUTD * 4 + 16)  // ~136 KB

__device__ __forceinline__ uint32_t smem_u32(const void* p) {
    uint32_t a;
    asm("{ .reg .u64 t; cvta.to.shared.u64 t, %1; cvt.u32.u64 %0, t; }"
        : "=r"(a) : "l"(p));
    return a;
}

__device__ __forceinline__ void ldsm4t(uint32_t& r0, uint32_t& r1,
                                       uint32_t& r2, uint32_t& r3, uint32_t addr) {
    asm volatile("ldmatrix.sync.aligned.m8n8.x4.trans.shared.b16 {%0,%1,%2,%3}, [%4];"
                 : "=r"(r0), "=r"(r1), "=r"(r2), "=r"(r3) : "r"(addr));
}

__device__ __forceinline__ void mma16816(float* d, const uint32_t* a,
                                         uint32_t b0, uint32_t b1) {
    asm volatile("mma.sync.aligned.m16n8k16.row.col.f32.bf16.bf16.f32 "
                 "{%0,%1,%2,%3}, {%4,%5,%6,%7}, {%8,%9}, {%0,%1,%2,%3};"
                 : "+f"(d[0]), "+f"(d[1]), "+f"(d[2]), "+f"(d[3])
                 : "r"(a[0]), "r"(a[1]), "r"(a[2]), "r"(a[3]), "r"(b0), "r"(b1));
}

__global__ void __launch_bounds__(256, 1)
density_mma(const float* __restrict__ t, const float* __restrict__ x,
            const float* __restrict__ w, const float* __restrict__ bias,
            float* __restrict__ out, int nstripes)
{
    extern __shared__ __align__(128) unsigned char smem[];
    __nv_bfloat16* whi = reinterpret_cast<__nv_bfloat16*>(smem + SM_WHI);
    __nv_bfloat16* wlo = reinterpret_cast<__nv_bfloat16*>(smem + SM_WLO);
    float* bs = reinterpret_cast<float*>(smem + SM_BIAS);

    const int tid = threadIdx.x;

    // ---- one-time: stage W as (hi, lo) bf16 with padded pitch + bias ----
    for (int e = tid; e < IND * OUTD; e += 256) {
        const int k = e >> 8, n = e & 255;
        const float v = w[e];
        const __nv_bfloat16 h = __float2bfloat16(v);
        whi[k * WPITCH + n] = h;
        wlo[k * WPITCH + n] = __float2bfloat16(v - __bfloat162float(h));
    }
    bs[tid] = bias[tid];
    __syncthreads();

    const int lane = tid & 31;
    const int gq   = lane >> 2;   // 0..7: row within stripe half
    const int qid  = lane & 3;    // 0..3: column quad
    const int gwarp  = blockIdx.x * 8 + (tid >> 5);
    const int nwarps = gridDim.x * 8;

    const uint32_t whi_u = smem_u32(whi);
    const uint32_t wlo_u = smem_u32(wlo);
    // ldmatrix row address lane layout (trans, x4): lanes 0-15 -> k rows at n0,
    // lanes 16-31 -> k rows at n0+8.
    const uint32_t lrow = (uint32_t)(lane & 15) * (WPITCH * 2);
    const uint32_t lcol = (uint32_t)((lane >> 4) << 3) * 2;

    for (int s = gwarp; s < nstripes; s += nwarps) {
        const int row0  = s << 4;
        const int row_a = row0 + gq;
        const int row_b = row_a + 8;

        // ---- load A (16 x 128) straight into mma fragments, hi+lo split ----
        uint32_t Ah[8][4], Al[8][4];
        #pragma unroll
        for (int ks = 0; ks < 8; ks++)
            #pragma unroll
            for (int q = 0; q < 2; q++)
                #pragma unroll
                for (int p = 0; p < 2; p++) {
                    const float2 v = *reinterpret_cast<const float2*>(
                        x + (size_t)(row0 + p * 8 + gq) * IND + ks * 16 + qid * 2 + q * 8);
                    const __nv_bfloat162 h = __floats2bfloat162_rn(v.x, v.y);
                    const float2 hf = __bfloat1622float2(h);
                    const __nv_bfloat162 l = __floats2bfloat162_rn(v.x - hf.x, v.y - hf.y);
                    Ah[ks][q * 2 + p] = *reinterpret_cast<const uint32_t*>(&h);
                    Al[ks][q * 2 + p] = *reinterpret_cast<const uint32_t*>(&l);
                }

        // ---- per-row softmax state + grid indices ----
        const float ta = __ldg(t + row_a), tb = __ldg(t + row_b);
        const float tga = ta * 255.0f, tgb = tb * 255.0f;
        const float Uaf = ceilf(tga),  Ubf = ceilf(tgb);
        const float intera = 1.0f - (Uaf - tga);
        const float interb = 1.0f - (Ubf - tgb);
        const int Uia = (int)Uaf, Uib = (int)Ubf;
        const int Lia = max(Uia - 1, 0), Lib = max(Uib - 1, 0);

        float sa = 0.f, sb = 0.f, gla = 0.f, glb = 0.f, gua = 0.f, gub = 0.f;

        // ---- 4 column chunks of 64 ----
        #pragma unroll
        for (int c = 0; c < 4; c++) {
            float acc[8][4];
            #pragma unroll
            for (int i = 0; i < 8; i++)
                #pragma unroll
                for (int j = 0; j < 4; j++) acc[i][j] = 0.f;

            #pragma unroll
            for (int ks = 0; ks < 8; ks++) {
                const uint32_t krow = (uint32_t)(ks * 16) * (WPITCH * 2);
                #pragma unroll
                for (int np = 0; np < 4; np++) {
                    const uint32_t boff = krow + lrow + (uint32_t)(c * 64 + np * 16) * 2 + lcol;
                    uint32_t h0, h1, h2, h3, l0, l1, l2, l3;
                    ldsm4t(h0, h1, h2, h3, whi_u + boff);
                    ldsm4t(l0, l1, l2, l3, wlo_u + boff);
                    mma16816(acc[np * 2 + 0], Ah[ks], h0, h1);   // hi*hi
                    mma16816(acc[np * 2 + 1], Ah[ks], h2, h3);
                    mma16816(acc[np * 2 + 0], Ah[ks], l0, l1);   // hi*lo
                    mma16816(acc[np * 2 + 1], Ah[ks], l2, l3);
                    mma16816(acc[np * 2 + 0], Al[ks], h0, h1);   // lo*hi
                    mma16816(acc[np * 2 + 1], Al[ks], h2, h3);
                }
            }

            // ---- chunk epilogue: exp + running sum + one-hot gather ----
            #pragma unroll
            for (int nt = 0; nt < 8; nt++) {
                const int col = c * 64 + nt * 8 + qid * 2;
                const float b0 = bs[col], b1 = bs[col + 1];
                const float e0 = __expf(acc[nt][0] + b0);
                const float e1 = __expf(acc[nt][1] + b1);
                const float e2 = __expf(acc[nt][2] + b0);
                const float e3 = __expf(acc[nt][3] + b1);
                sa += e0 + e1;
                sb += e2 + e3;
                if (col == Lia)     gla = e0;
                if (col + 1 == Lia) gla = e1;
                if (col == Uia)     gua = e0;
                if (col + 1 == Uia) gua = e1;
                if (col == Lib)     glb = e2;
                if (col + 1 == Lib) glb = e3;
                if (col == Uib)     gub = e2;
                if (col + 1 == Uib) gub = e3;
            }
        }

        // ---- reduce across the 4-thread column quad ----
        #pragma unroll
        for (int d = 1; d < 4; d <<= 1) {
            sa  += __shfl_xor_sync(0xffffffffu, sa,  d);
            sb  += __shfl_xor_sync(0xffffffffu, sb,  d);
            gla += __shfl_xor_sync(0xffffffffu, gla, d);
            gua += __shfl_xor_sync(0xffffffffu, gua, d);
            glb += __shfl_xor_sync(0xffffffffu, glb, d);
            gub += __shfl_xor_sync(0xffffffffu, gub, d);
        }
        if (qid == 0) {
            out[row_a] = __fdividef(gla + (gua - gla) * intera, sa);
            out[row_b] = __fdividef(glb + (gub - glb) * interb, sb);
        }
    }
}

extern "C" void kernel_launch(void* const* d_in, const int* in_sizes, int n_in,
                              void* d_out, int out_size)
{
    const float* t    = (const float*)d_in[0];
    const float* x    = (const float*)d_in[1];
    const float* w    = (const float*)d_in[2];
    const float* bias = (const float*)d_in[3];
    float* out        = (float*)d_out;

    const int n        = in_sizes[0];
    const int nstripes = n >> 4;       // 32768

    int dev = 0, smc = 0;
    cudaGetDevice(&dev);
    cudaDeviceGetAttribute(&smc, cudaDevAttrMultiProcessorCount, dev);
    if (smc <= 0) smc = 148;

    cudaFuncSetAttribute(density_mma,
                         cudaFuncAttributeMaxDynamicSharedMemorySize, SM_TOTAL);
    density_mma<<<smc, 256, SM_TOTAL>>>(t, x, w, bias, out, nstripes);
}

// round 4
// speedup vs baseline: 3.6844x; 1.0824x over previous
#include <cuda_runtime.h>
#include <cuda_bf16.h>
#include <cstdint>

// ============================================================================
// Density_Block via bf16 mma.sync m16n8k16, split-precision (3 products).
// out[i] = lerp of softmax(x[i,:] @ W + b) at data-dependent cols L/U.
// N=524288, IND=128, OUTD=256.
// Persistent: W (hi/lo bf16) in smem once; 12 warps/SM stream 16-row stripes.
// ============================================================================

#define IND    128
#define OUTD   256
#define WPITCH 264      // padded bf16 pitch: 528B row stride -> conflict-free ldmatrix
#define NTHR   384

#define SM_WHI  0
#define SM_WLO  (IND * WPITCH * 2)          // 67584
#define SM_BIAS (2 * IND * WPITCH * 2)      // 135168
#define SM_TOTAL (SM_BIAS + OUTD * 4 + 16)

__device__ __forceinline__ uint32_t smem_u32(const void* p) {
    uint32_t a;
    asm("{ .reg .u64 t; cvta.to.shared.u64 t, %1; cvt.u32.u64 %0, t; }"
        : "=r"(a) : "l"(p));
    return a;
}

__device__ __forceinline__ void ldsm4t(uint32_t& r0, uint32_t& r1,
                                       uint32_t& r2, uint32_t& r3, uint32_t addr) {
    asm volatile("ldmatrix.sync.aligned.m8n8.x4.trans.shared.b16 {%0,%1,%2,%3}, [%4];"
                 : "=r"(r0), "=r"(r1), "=r"(r2), "=r"(r3) : "r"(addr));
}

__device__ __forceinline__ void mma16816(float* d, const uint32_t* a,
                                         uint32_t b0, uint32_t b1) {
    asm volatile("mma.sync.aligned.m16n8k16.row.col.f32.bf16.bf16.f32 "
                 "{%0,%1,%2,%3}, {%4,%5,%6,%7}, {%8,%9}, {%0,%1,%2,%3};"
                 : "+f"(d[0]), "+f"(d[1]), "+f"(d[2]), "+f"(d[3])
                 : "r"(a[0]), "r"(a[1]), "r"(a[2]), "r"(a[3]), "r"(b0), "r"(b1));
}

__global__ void __launch_bounds__(NTHR, 1)
density_mma(const float* __restrict__ t, const float* __restrict__ x,
            const float* __restrict__ w, const float* __restrict__ bias,
            float* __restrict__ out, int nstripes)
{
    extern __shared__ __align__(128) unsigned char smem[];
    __nv_bfloat16* whi = reinterpret_cast<__nv_bfloat16*>(smem + SM_WHI);
    __nv_bfloat16* wlo = reinterpret_cast<__nv_bfloat16*>(smem + SM_WLO);
    float* bs = reinterpret_cast<float*>(smem + SM_BIAS);

    const int tid = threadIdx.x;

    // ---- one-time: stage W as (hi, lo) bf16 with padded pitch + bias ----
    for (int e = tid; e < IND * OUTD; e += NTHR) {
        const int k = e >> 8, n = e & 255;
        const float v = w[e];
        const __nv_bfloat16 h = __float2bfloat16(v);
        whi[k * WPITCH + n] = h;
        wlo[k * WPITCH + n] = __float2bfloat16(v - __bfloat162float(h));
    }
    if (tid < OUTD) bs[tid] = bias[tid];
    __syncthreads();

    const int lane = tid & 31;
    const int gq   = lane >> 2;   // 0..7: row within stripe half
    const int qid  = lane & 3;    // 0..3: column quad
    const int gwarp  = blockIdx.x * (NTHR / 32) + (tid >> 5);
    const int nwarps = gridDim.x * (NTHR / 32);

    const uint32_t whi_u = smem_u32(whi);
    const uint32_t wlo_u = smem_u32(wlo);
    // ldmatrix.trans x4 lane addressing: lanes 0-15 -> k rows at n0, 16-31 -> n0+8
    const uint32_t lrow = (uint32_t)(lane & 15) * (WPITCH * 2);
    const uint32_t lcol = (uint32_t)((lane >> 4) << 3) * 2;

    for (int s = gwarp; s < nstripes; s += nwarps) {
        const int row0  = s << 4;
        const int row_a = row0 + gq;
        const int row_b = row_a + 8;

        // ---- load A (16 x 128) straight into mma fragments, hi+lo split ----
        uint32_t Ah[8][4], Al[8][4];
        #pragma unroll
        for (int ks = 0; ks < 8; ks++)
            #pragma unroll
            for (int q = 0; q < 2; q++)
                #pragma unroll
                for (int p = 0; p < 2; p++) {
                    const float2 v = *reinterpret_cast<const float2*>(
                        x + (size_t)(row0 + p * 8 + gq) * IND + ks * 16 + qid * 2 + q * 8);
                    const __nv_bfloat162 h = __floats2bfloat162_rn(v.x, v.y);
                    const float2 hf = __bfloat1622float2(h);
                    const __nv_bfloat162 l = __floats2bfloat162_rn(v.x - hf.x, v.y - hf.y);
                    Ah[ks][q * 2 + p] = *reinterpret_cast<const uint32_t*>(&h);
                    Al[ks][q * 2 + p] = *reinterpret_cast<const uint32_t*>(&l);
                }

        // ---- per-row grid indices / softmax state ----
        const float ta = __ldg(t + row_a), tb = __ldg(t + row_b);
        const float tga = ta * 255.0f, tgb = tb * 255.0f;
        const float Uaf = ceilf(tga),  Ubf = ceilf(tgb);
        const float intera = 1.0f - (Uaf - tga);
        const float interb = 1.0f - (Ubf - tgb);
        const int Uia = (int)Uaf, Uib = (int)Ubf;
        const int Lia = max(Uia - 1, 0), Lib = max(Uib - 1, 0);

        float sa = 0.f, sb = 0.f, gla = 0.f, glb = 0.f, gua = 0.f, gub = 0.f;

        // ---- 8 column chunks of 32 (rolled loop: small I$ footprint) ----
        for (int c = 0; c < 8; c++) {
            float acc[4][4];
            #pragma unroll
            for (int i = 0; i < 4; i++)
                #pragma unroll
                for (int j = 0; j < 4; j++) acc[i][j] = 0.f;

            const uint32_t cbyte = (uint32_t)(c * 32) * 2 + lrow + lcol;

            #pragma unroll
            for (int ks = 0; ks < 8; ks++) {
                const uint32_t boff = (uint32_t)(ks * 16) * (WPITCH * 2) + cbyte;
                uint32_t h0, h1, h2, h3, h4, h5, h6, h7;
                uint32_t l0, l1, l2, l3, l4, l5, l6, l7;
                ldsm4t(h0, h1, h2, h3, whi_u + boff);
                ldsm4t(h4, h5, h6, h7, whi_u + boff + 32);
                ldsm4t(l0, l1, l2, l3, wlo_u + boff);
                ldsm4t(l4, l5, l6, l7, wlo_u + boff + 32);
                // phase 1: hi*hi (4 independent accs)
                mma16816(acc[0], Ah[ks], h0, h1);
                mma16816(acc[1], Ah[ks], h2, h3);
                mma16816(acc[2], Ah[ks], h4, h5);
                mma16816(acc[3], Ah[ks], h6, h7);
                // phase 2: hi*lo
                mma16816(acc[0], Ah[ks], l0, l1);
                mma16816(acc[1], Ah[ks], l2, l3);
                mma16816(acc[2], Ah[ks], l4, l5);
                mma16816(acc[3], Ah[ks], l6, l7);
                // phase 3: lo*hi
                mma16816(acc[0], Al[ks], h0, h1);
                mma16816(acc[1], Al[ks], h2, h3);
                mma16816(acc[2], Al[ks], h4, h5);
                mma16816(acc[3], Al[ks], h6, h7);
            }

            // ---- chunk epilogue: exp + running sum + one-hot gather ----
            #pragma unroll
            for (int nt = 0; nt < 4; nt++) {
                const int col = c * 32 + nt * 8 + qid * 2;
                const float b0 = bs[col], b1 = bs[col + 1];
                const float e0 = __expf(acc[nt][0] + b0);
                const float e1 = __expf(acc[nt][1] + b1);
                const float e2 = __expf(acc[nt][2] + b0);
                const float e3 = __expf(acc[nt][3] + b1);
                sa += e0 + e1;
                sb += e2 + e3;
                if (col == Lia)     gla = e0;
                if (col + 1 == Lia) gla = e1;
                if (col == Uia)     gua = e0;
                if (col + 1 == Uia) gua = e1;
                if (col == Lib)     glb = e2;
                if (col + 1 == Lib) glb = e3;
                if (col == Uib)     gub = e2;
                if (col + 1 == Uib) gub = e3;
            }
        }

        // ---- reduce across the 4-thread column quad ----
        #pragma unroll
        for (int d = 1; d < 4; d <<= 1) {
            sa  += __shfl_xor_sync(0xffffffffu, sa,  d);
            sb  += __shfl_xor_sync(0xffffffffu, sb,  d);
            gla += __shfl_xor_sync(0xffffffffu, gla, d);
            gua += __shfl_xor_sync(0xffffffffu, gua, d);
            glb += __shfl_xor_sync(0xffffffffu, glb, d);
            gub += __shfl_xor_sync(0xffffffffu, gub, d);
        }
        if (qid == 0) {
            out[row_a] = __fdividef(gla + (gua - gla) * intera, sa);
            out[row_b] = __fdividef(glb + (gub - glb) * interb, sb);
        }
    }
}

extern "C" void kernel_launch(void* const* d_in, const int* in_sizes, int n_in,
                              void* d_out, int out_size)
{
    const float* t    = (const float*)d_in[0];
    const float* x    = (const float*)d_in[1];
    const float* w    = (const float*)d_in[2];
    const float* bias = (const float*)d_in[3];
    float* out        = (float*)d_out;

    const int n        = in_sizes[0];
    const int nstripes = n >> 4;       // 32768

    int dev = 0, smc = 0;
    cudaGetDevice(&dev);
    cudaDeviceGetAttribute(&smc, cudaDevAttrMultiProcessorCount, dev);
    if (smc <= 0) smc = 148;

    cudaFuncSetAttribute(density_mma,
                         cudaFuncAttributeMaxDynamicSharedMemorySize, SM_TOTAL);
    density_mma<<<smc, NTHR, SM_TOTAL>>>(t, x, w, bias, out, nstripes);
}

// round 5
// speedup vs baseline: 3.8884x; 1.0554x over previous
#include <cuda_runtime.h>
#include <cuda_bf16.h>
#include <cstdint>

// ============================================================================
// Density_Block via bf16 mma.sync m16n8k16, split-precision (3 products).
// out[i] = lerp of softmax(x[i,:] @ W + b) at data-dependent cols L/U.
// N=524288, IND=128, OUTD=256.
// Persistent: W (hi/lo bf16) in smem once; 16 warps/SM stream 16-row stripes.
// ============================================================================

#define IND    128
#define OUTD   256
#define WPITCH 264      // padded bf16 pitch: 528B row stride -> conflict-free ldmatrix
#define NTHR   512

#define SM_WHI  0
#define SM_WLO  (IND * WPITCH * 2)          // 67584
#define SM_BIAS (2 * IND * WPITCH * 2)      // 135168
#define SM_TOTAL (SM_BIAS + OUTD * 4 + 16)

#define LOG2E 1.4426950408889634f

__device__ __forceinline__ uint32_t smem_u32(const void* p) {
    uint32_t a;
    asm("{ .reg .u64 t; cvta.to.shared.u64 t, %1; cvt.u32.u64 %0, t; }"
        : "=r"(a) : "l"(p));
    return a;
}

__device__ __forceinline__ float ex2f(float v) {
    float r;
    asm("ex2.approx.f32 %0, %1;" : "=f"(r) : "f"(v));
    return r;
}

__device__ __forceinline__ void ldsm4t(uint32_t& r0, uint32_t& r1,
                                       uint32_t& r2, uint32_t& r3, uint32_t addr) {
    asm volatile("ldmatrix.sync.aligned.m8n8.x4.trans.shared.b16 {%0,%1,%2,%3}, [%4];"
                 : "=r"(r0), "=r"(r1), "=r"(r2), "=r"(r3) : "r"(addr));
}

__device__ __forceinline__ void mma16816(float* d, const uint32_t* a,
                                         uint32_t b0, uint32_t b1) {
    asm volatile("mma.sync.aligned.m16n8k16.row.col.f32.bf16.bf16.f32 "
                 "{%0,%1,%2,%3}, {%4,%5,%6,%7}, {%8,%9}, {%0,%1,%2,%3};"
                 : "+f"(d[0]), "+f"(d[1]), "+f"(d[2]), "+f"(d[3])
                 : "r"(a[0]), "r"(a[1]), "r"(a[2]), "r"(a[3]), "r"(b0), "r"(b1));
}

__global__ void __launch_bounds__(NTHR, 1)
density_mma(const float* __restrict__ t, const float* __restrict__ x,
            const float* __restrict__ w, const float* __restrict__ bias,
            float* __restrict__ out, int nstripes)
{
    extern __shared__ __align__(128) unsigned char smem[];
    __nv_bfloat16* whi = reinterpret_cast<__nv_bfloat16*>(smem + SM_WHI);
    __nv_bfloat16* wlo = reinterpret_cast<__nv_bfloat16*>(smem + SM_WLO);
    float* bs = reinterpret_cast<float*>(smem + SM_BIAS);   // bias * log2e

    const int tid = threadIdx.x;

    // ---- one-time: stage W as (hi, lo) bf16 with padded pitch + scaled bias ----
    for (int e = tid; e < IND * OUTD; e += NTHR) {
        const int k = e >> 8, n = e & 255;
        const float v = w[e];
        const __nv_bfloat16 h = __float2bfloat16(v);
        whi[k * WPITCH + n] = h;
        wlo[k * WPITCH + n] = __float2bfloat16(v - __bfloat162float(h));
    }
    if (tid < OUTD) bs[tid] = bias[tid] * LOG2E;
    __syncthreads();

    const int lane = tid & 31;
    const int gq   = lane >> 2;   // 0..7: row within stripe half
    const int qid  = lane & 3;    // 0..3: column quad
    const int gwarp  = blockIdx.x * (NTHR / 32) + (tid >> 5);
    const int nwarps = gridDim.x * (NTHR / 32);

    const uint32_t whi_u = smem_u32(whi);
    const uint32_t wlo_u = smem_u32(wlo);
    // ldmatrix.trans x4 lane addressing: lanes 0-15 -> k rows at n0, 16-31 -> n0+8
    const uint32_t lrow = (uint32_t)(lane & 15) * (WPITCH * 2);
    const uint32_t lcol = (uint32_t)((lane >> 4) << 3) * 2;

    for (int s = gwarp; s < nstripes; s += nwarps) {
        const int row0  = s << 4;
        const int row_a = row0 + gq;
        const int row_b = row_a + 8;

        // ---- load A (16 x 128) straight into mma fragments, hi+lo split ----
        uint32_t Ah[8][4], Al[8][4];
        #pragma unroll
        for (int ks = 0; ks < 8; ks++)
            #pragma unroll
            for (int q = 0; q < 2; q++)
                #pragma unroll
                for (int p = 0; p < 2; p++) {
                    const float2 v = *reinterpret_cast<const float2*>(
                        x + (size_t)(row0 + p * 8 + gq) * IND + ks * 16 + qid * 2 + q * 8);
                    const __nv_bfloat162 h = __floats2bfloat162_rn(v.x, v.y);
                    const float2 hf = __bfloat1622float2(h);
                    const __nv_bfloat162 l = __floats2bfloat162_rn(v.x - hf.x, v.y - hf.y);
                    Ah[ks][q * 2 + p] = *reinterpret_cast<const uint32_t*>(&h);
                    Al[ks][q * 2 + p] = *reinterpret_cast<const uint32_t*>(&l);
                }

        // ---- per-row grid indices / softmax state ----
        const float ta = __ldg(t + row_a), tb = __ldg(t + row_b);
        const float tga = ta * 255.0f, tgb = tb * 255.0f;
        const float Uaf = ceilf(tga),  Ubf = ceilf(tgb);
        const float intera = 1.0f - (Uaf - tga);
        const float interb = 1.0f - (Ubf - tgb);
        const int Uia = (int)Uaf, Uib = (int)Ubf;
        const int Lia = max(Uia - 1, 0), Lib = max(Uib - 1, 0);

        float sa = 0.f, sb = 0.f, gla = 0.f, glb = 0.f, gua = 0.f, gub = 0.f;

        // ---- 8 column chunks of 32 (rolled loop: small I$ footprint) ----
        for (int c = 0; c < 8; c++) {
            float acc[4][4];
            #pragma unroll
            for (int i = 0; i < 4; i++)
                #pragma unroll
                for (int j = 0; j < 4; j++) acc[i][j] = 0.f;

            const uint32_t cbyte = (uint32_t)(c * 32) * 2 + lrow + lcol;

            #pragma unroll
            for (int ks = 0; ks < 8; ks++) {
                const uint32_t boff = (uint32_t)(ks * 16) * (WPITCH * 2) + cbyte;
                uint32_t h0, h1, h2, h3, h4, h5, h6, h7;
                uint32_t l0, l1, l2, l3, l4, l5, l6, l7;
                ldsm4t(h0, h1, h2, h3, whi_u + boff);
                ldsm4t(h4, h5, h6, h7, whi_u + boff + 32);
                ldsm4t(l0, l1, l2, l3, wlo_u + boff);
                ldsm4t(l4, l5, l6, l7, wlo_u + boff + 32);
                // phase 1: hi*hi (4 independent accs)
                mma16816(acc[0], Ah[ks], h0, h1);
                mma16816(acc[1], Ah[ks], h2, h3);
                mma16816(acc[2], Ah[ks], h4, h5);
                mma16816(acc[3], Ah[ks], h6, h7);
                // phase 2: hi*lo
                mma16816(acc[0], Ah[ks], l0, l1);
                mma16816(acc[1], Ah[ks], l2, l3);
                mma16816(acc[2], Ah[ks], l4, l5);
                mma16816(acc[3], Ah[ks], l6, l7);
                // phase 3: lo*hi
                mma16816(acc[0], Al[ks], h0, h1);
                mma16816(acc[1], Al[ks], h2, h3);
                mma16816(acc[2], Al[ks], h4, h5);
                mma16816(acc[3], Al[ks], h6, h7);
            }

            // ---- chunk epilogue: exp2(acc*log2e + b2) + sum + one-hot gather ----
            #pragma unroll
            for (int nt = 0; nt < 4; nt++) {
                const int col = c * 32 + nt * 8 + qid * 2;
                const float b0 = bs[col], b1 = bs[col + 1];
                const float e0 = ex2f(fmaf(acc[nt][0], LOG2E, b0));
                const float e1 = ex2f(fmaf(acc[nt][1], LOG2E, b1));
                const float e2 = ex2f(fmaf(acc[nt][2], LOG2E, b0));
                const float e3 = ex2f(fmaf(acc[nt][3], LOG2E, b1));
                sa += e0 + e1;
                sb += e2 + e3;
                if (col == Lia)     gla = e0;
                if (col + 1 == Lia) gla = e1;
                if (col == Uia)     gua = e0;
                if (col + 1 == Uia) gua = e1;
                if (col == Lib)     glb = e2;
                if (col + 1 == Lib) glb = e3;
                if (col == Uib)     gub = e2;
                if (col + 1 == Uib) gub = e3;
            }
        }

        // ---- reduce across the 4-thread column quad ----
        #pragma unroll
        for (int d = 1; d < 4; d <<= 1) {
            sa  += __shfl_xor_sync(0xffffffffu, sa,  d);
            sb  += __shfl_xor_sync(0xffffffffu, sb,  d);
            gla += __shfl_xor_sync(0xffffffffu, gla, d);
            gua += __shfl_xor_sync(0xffffffffu, gua, d);
            glb += __shfl_xor_sync(0xffffffffu, glb, d);
            gub += __shfl_xor_sync(0xffffffffu, gub, d);
        }
        if (qid == 0) {
            out[row_a] = __fdividef(gla + (gua - gla) * intera, sa);
            out[row_b] = __fdividef(glb + (gub - glb) * interb, sb);
        }
    }
}

extern "C" void kernel_launch(void* const* d_in, const int* in_sizes, int n_in,
                              void* d_out, int out_size)
{
    const float* t    = (const float*)d_in[0];
    const float* x    = (const float*)d_in[1];
    const float* w    = (const float*)d_in[2];
    const float* bias = (const float*)d_in[3];
    float* out        = (float*)d_out;

    const int n        = in_sizes[0];
    const int nstripes = n >> 4;       // 32768

    int dev = 0, smc = 0;
    cudaGetDevice(&dev);
    cudaDeviceGetAttribute(&smc, cudaDevAttrMultiProcessorCount, dev);
    if (smc <= 0) smc = 148;

    cudaFuncSetAttribute(density_mma,
                         cudaFuncAttributeMaxDynamicSharedMemorySize, SM_TOTAL);
    density_mma<<<smc, NTHR, SM_TOTAL>>>(t, x, w, bias, out, nstripes);
}